// round 2
// baseline (speedup 1.0000x reference)
#include <cuda_runtime.h>

// Problem constants
#define NB 1024
#define TPTS 512
#define CTXN 23
#define D 320
#define NL 5
#define NH 8
#define DHD 40
#define FFD 1280
#define NCOEF 49
#define S 24
#define NT 320          // threads per CTA (10 warps)
#define NWARP 10
#define QVS 965         // padded row stride for qkv smem (conflict-free: gcd(965%32=5,32)=1)
#define HS 26           // padded transposed-activation row stride (24 rows + 2 pad, 8B-aligned)

// Shared-memory layout (in floats)
#define XS_OFF 0                         // x residual   [24][320]      7680
#define HST_OFF 7680                     // LN out (T)   [320][26]      8320
#define QV_OFF 16000                     // qkv          [24][965]      23160  (aliased: ffn gelu tile / head u)
#define SC_OFF 39160                     // scores       [8][24][25]    4800
#define HH_OFF 43960                     // head LN vec  [320]
#define CC_OFF 44280                     // cheb coeffs  [64]
#define ST_OFF 44344                     // stats        [8]
#define SMEM_FLOATS 44352
#define SMEM_BYTES (SMEM_FLOATS * 4)

// Transposed weights, [layer][k][o] so per-thread (thread = output col) LDG is coalesced.
__device__ float g_Wint[NL * 320 * 960];
__device__ float g_Woutt[NL * 320 * 320];
__device__ float g_W1t[NL * 320 * 1280];
__device__ float g_W2t[NL * 1280 * 320];   // [l][ff][d]
__device__ float g_Wh1t[320 * 320];

__global__ void prep_kernel(const float* __restrict__ Win, const float* __restrict__ Wout,
                            const float* __restrict__ W1, const float* __restrict__ W2,
                            const float* __restrict__ Wh1) {
    long start = (long)blockIdx.x * blockDim.x + threadIdx.x;
    long stride = (long)gridDim.x * blockDim.x;
    for (long i = start; i < (long)NL * 960 * 320; i += stride) {
        long c = i / 307200, rem = i % 307200;
        long k = rem / 960, o = rem % 960;
        g_Wint[i] = Win[c * 307200 + o * 320 + k];
    }
    for (long i = start; i < (long)NL * 320 * 320; i += stride) {
        long c = i / 102400, rem = i % 102400;
        long k = rem / 320, o = rem % 320;
        g_Woutt[i] = Wout[c * 102400 + o * 320 + k];
    }
    for (long i = start; i < (long)NL * 320 * 1280; i += stride) {
        long c = i / 409600, rem = i % 409600;
        long k = rem / 1280, o = rem % 1280;
        g_W1t[i] = W1[c * 409600 + o * 320 + k];
    }
    for (long i = start; i < (long)NL * 1280 * 320; i += stride) {
        long c = i / 409600, rem = i % 409600;
        long f = rem / 320, d = rem % 320;
        g_W2t[i] = W2[c * 409600 + d * 1280 + f];
    }
    for (long i = start; i < (long)320 * 320; i += stride) {
        long k = i / 320, o = i % 320;
        g_Wh1t[i] = Wh1[o * 320 + k];
    }
}

__device__ __forceinline__ unsigned long long ffma2(unsigned long long a, unsigned long long b,
                                                    unsigned long long c) {
    unsigned long long d;
    asm("fma.rn.f32x2 %0, %1, %2, %3;" : "=l"(d) : "l"(a), "l"(b), "l"(c));
    return d;
}
__device__ __forceinline__ unsigned long long bcast2(float x) {
    unsigned long long d;
    asm("mov.b64 %0, {%1, %1};" : "=l"(d) : "f"(x));
    return d;
}
__device__ __forceinline__ float2 unpack2(unsigned long long a) {
    float2 v;
    asm("mov.b64 {%0, %1}, %2;" : "=f"(v.x), "=f"(v.y) : "l"(a));
    return v;
}
__device__ __forceinline__ float gelu_exact(float x) {
    return 0.5f * x * (1.0f + erff(x * 0.70710678118654752f));
}
__device__ __forceinline__ float warp_sum(float v) {
#pragma unroll
    for (int o = 16; o; o >>= 1) v += __shfl_xor_sync(0xffffffffu, v, o);
    return v;
}

// C[r][o] = sum_k hin_T[k][r] * Wt[k][o] for all 24 rows, one output column o per call.
// hin is transposed+padded [320][HS]; row pairs read as LDS.64 broadcast -> fma.rn.f32x2.
__device__ __forceinline__ void gemm24(const float* __restrict__ Wt, int NO, int o,
                                       const float* __restrict__ hin, float2* res) {
    unsigned long long acc[12];
#pragma unroll
    for (int p = 0; p < 12; p++) acc[p] = 0ull;
    const float* wp = Wt + o;
#pragma unroll 4
    for (int k = 0; k < 320; k++) {
        unsigned long long w2 = bcast2(*wp);
        wp += NO;
        const unsigned long long* hp = (const unsigned long long*)(hin + k * HS);
#pragma unroll
        for (int p = 0; p < 12; p++) acc[p] = ffma2(w2, hp[p], acc[p]);
    }
#pragma unroll
    for (int p = 0; p < 12; p++) res[p] = unpack2(acc[p]);
}

// LayerNorm of xs[24][320] -> transposed hst[k][HS]+r, two-pass per row, one warp per row.
__device__ __forceinline__ void layernorm24(const float* __restrict__ xs, float* __restrict__ hst,
                                            const float* __restrict__ w, const float* __restrict__ b,
                                            int warp, int lane) {
    for (int r = warp; r < S; r += NWARP) {
        const float* row = xs + r * D;
        float s = 0.f;
        for (int k = lane; k < D; k += 32) s += row[k];
        s = warp_sum(s);
        float mean = s * (1.f / D);
        float s2 = 0.f;
        for (int k = lane; k < D; k += 32) {
            float v = row[k] - mean;
            s2 += v * v;
        }
        s2 = warp_sum(s2);
        float rstd = rsqrtf(s2 * (1.f / D) + 1e-5f);
        for (int k = lane; k < D; k += 32)
            hst[k * HS + r] = (row[k] - mean) * rstd * w[k] + b[k];
    }
}

__global__ __launch_bounds__(NT, 1) void fused_kernel(
    const float* __restrict__ k_norm, const float* __restrict__ ctx,
    const float* __restrict__ W_e, const float* __restrict__ b_e,
    const float* __restrict__ cls,
    const float* __restrict__ ln1_w, const float* __restrict__ ln1_b,
    const float* __restrict__ b_in, const float* __restrict__ b_out,
    const float* __restrict__ ln2_w, const float* __restrict__ ln2_b,
    const float* __restrict__ b1, const float* __restrict__ b2,
    const float* __restrict__ hln_w, const float* __restrict__ hln_b,
    const float* __restrict__ bh1, const float* __restrict__ Wh2,
    const float* __restrict__ bh2, float* __restrict__ out) {
    extern __shared__ float sm[];
    float* xs = sm + XS_OFF;
    float* hst = sm + HST_OFF;
    float* qv = sm + QV_OFF;
    float* sc = sm + SC_OFF;

    const int b = blockIdx.x;
    const int tid = threadIdx.x;
    const int warp = tid >> 5;
    const int lane = tid & 31;

    // ---- build x: row 0 = cls, rows 1..23 = ctx*W_e + b_e ----
    for (int i = tid; i < S * D; i += NT) {
        int r = i / D, d = i % D;
        xs[i] = (r == 0) ? cls[d] : ctx[(long)b * CTXN + (r - 1)] * W_e[d] + b_e[d];
    }
    __syncthreads();

    for (int l = 0; l < NL; l++) {
        // ---- LN1 ----
        layernorm24(xs, hst, ln1_w + l * D, ln1_b + l * D, warp, lane);
        __syncthreads();

        // ---- QKV GEMM: qv[r][o] = b_in[o] + hst . W_in^T ----
        for (int c = 0; c < 3; c++) {
            int o = c * NT + tid;
            float2 res[12];
            gemm24(g_Wint + (long)l * 307200, 960, o, hst, res);
            float bias = b_in[l * 960 + o];
#pragma unroll
            for (int p = 0; p < 12; p++) {
                qv[(2 * p) * QVS + o] = res[p].x + bias;
                qv[(2 * p + 1) * QVS + o] = res[p].y + bias;
            }
        }
        __syncthreads();

        // ---- attention: one warp per head; output written transposed into hst ----
        if (warp < NH) {
            const int h = warp;
            const float scale = 0.15811388300841897f;  // 1/sqrt(40)
            for (int idx = lane; idx < S * S; idx += 32) {
                int qr = idx / S, kc = idx % S;
                const float* qp = qv + qr * QVS + h * DHD;
                const float* kp = qv + kc * QVS + D + h * DHD;
                float s = 0.f;
#pragma unroll
                for (int d = 0; d < DHD; d++) s += qp[d] * kp[d];
                sc[(h * S + qr) * 25 + kc] = s * scale;
            }
            __syncwarp();
            if (lane < S) {
                float* row = sc + (h * S + lane) * 25;
                float mx = -1e30f;
#pragma unroll
                for (int c = 0; c < S; c++) mx = fmaxf(mx, row[c]);
                float sum = 0.f;
#pragma unroll
                for (int c = 0; c < S; c++) {
                    float e = expf(row[c] - mx);
                    row[c] = e;
                    sum += e;
                }
                float inv = 1.f / sum;
#pragma unroll
                for (int c = 0; c < S; c++) row[c] *= inv;
            }
            __syncwarp();
            for (int idx = lane; idx < S * DHD; idx += 32) {
                int r = idx / DHD, d = idx % DHD;
                const float* ar = sc + (h * S + r) * 25;
                const float* vp = qv + 2 * D + h * DHD + d;
                float s = 0.f;
#pragma unroll
                for (int c = 0; c < S; c++) s += ar[c] * vp[c * QVS];
                hst[(h * DHD + d) * HS + r] = s;  // transposed attn output
            }
        }
        __syncthreads();

        // ---- output projection (residual add) ----
        {
            int o = tid;
            float2 res[12];
            gemm24(g_Woutt + (long)l * 102400, 320, o, hst, res);
            float bias = b_out[l * D + o];
#pragma unroll
            for (int p = 0; p < 12; p++) {
                xs[(2 * p) * D + o] += res[p].x + bias;
                xs[(2 * p + 1) * D + o] += res[p].y + bias;
            }
        }
        __syncthreads();

        // ---- LN2 ----
        layernorm24(xs, hst, ln2_w + l * D, ln2_b + l * D, warp, lane);
        __syncthreads();

        // ---- FFN streamed in 4 chunks of 320 (gelu tile aliases qv) ----
        float* gstc = qv;  // [320][HS]
        for (int c = 0; c < 4; c++) {
            {
                int o = c * NT + tid;
                float2 res[12];
                gemm24(g_W1t + (long)l * 409600, 1280, o, hst, res);
                float bias = b1[l * FFD + o];
#pragma unroll
                for (int p = 0; p < 12; p++) {
                    gstc[tid * HS + 2 * p] = gelu_exact(res[p].x + bias);
                    gstc[tid * HS + 2 * p + 1] = gelu_exact(res[p].y + bias);
                }
            }
            __syncthreads();
            {
                int o = tid;
                float2 res[12];
                gemm24(g_W2t + (long)l * 409600 + (long)c * NT * D, 320, o, gstc, res);
                float bias = (c == 0) ? b2[l * D + o] : 0.f;
#pragma unroll
                for (int p = 0; p < 12; p++) {
                    xs[(2 * p) * D + o] += res[p].x + bias;
                    xs[(2 * p + 1) * D + o] += res[p].y + bias;
                }
            }
            __syncthreads();
        }
    }

    // ---- head: LN(x[0]) ----
    if (warp == 0) {
        float s = 0.f;
        for (int k = lane; k < D; k += 32) s += xs[k];
        s = warp_sum(s);
        float mean = s * (1.f / D);
        float s2 = 0.f;
        for (int k = lane; k < D; k += 32) {
            float v = xs[k] - mean;
            s2 += v * v;
        }
        s2 = warp_sum(s2);
        if (lane == 0) {
            sm[ST_OFF] = mean;
            sm[ST_OFF + 1] = rsqrtf(s2 * (1.f / D) + 1e-5f);
        }
    }
    __syncthreads();
    {
        float mean = sm[ST_OFF], rstd = sm[ST_OFF + 1];
        int k = tid;  // NT == D
        sm[HH_OFF + k] = (xs[k] - mean) * rstd * hln_w[k] + hln_b[k];
    }
    __syncthreads();

    // ---- u = gelu(hh @ Wh1^T + bh1): one output per thread (u aliases qv) ----
    {
        int o = tid;
        float acc = bh1[o];
        const float* wp = g_Wh1t + o;
        const float* hh = sm + HH_OFF;
#pragma unroll 4
        for (int k = 0; k < D; k++) {
            acc = fmaf(hh[k], *wp, acc);
            wp += D;
        }
        qv[o] = gelu_exact(acc);
    }
    __syncthreads();

    // ---- c[j] = u @ Wh2^T + bh2 (warp-per-coefficient reduce, coalesced) ----
    for (int j = warp; j < NCOEF; j += NWARP) {
        float s = 0.f;
        for (int k = lane; k < D; k += 32) s += qv[k] * Wh2[j * D + k];
        s = warp_sum(s);
        if (lane == 0) sm[CC_OFF + j] = s + bh2[j];
    }
    __syncthreads();

    // ---- Chebyshev sum + sigmoid over T=512 points ----
    const float* cc = sm + CC_OFF;
    for (int t = tid; t < TPTS; t += NT) {
        float x = k_norm[(long)b * TPTS + t];
        float tp = 1.f, tc = x;
        float z = cc[0] + cc[1] * x;
#pragma unroll
        for (int n = 2; n < NCOEF; n++) {
            float tn = 2.f * x * tc - tp;
            z = fmaf(cc[n], tn, z);
            tp = tc;
            tc = tn;
        }
        out[(long)b * TPTS + t] = 1.f / (1.f + expf(-z));
    }
}

extern "C" void kernel_launch(void* const* d_in, const int* in_sizes, int n_in,
                              void* d_out, int out_size) {
    (void)in_sizes; (void)n_in; (void)out_size;
    const float* k_norm = (const float*)d_in[0];
    const float* ctx = (const float*)d_in[1];
    const float* W_e = (const float*)d_in[2];
    const float* b_e = (const float*)d_in[3];
    const float* cls = (const float*)d_in[4];
    const float* ln1_w = (const float*)d_in[5];
    const float* ln1_b = (const float*)d_in[6];
    const float* W_in = (const float*)d_in[7];
    const float* b_in = (const float*)d_in[8];
    const float* W_out = (const float*)d_in[9];
    const float* b_out = (const float*)d_in[10];
    const float* ln2_w = (const float*)d_in[11];
    const float* ln2_b = (const float*)d_in[12];
    const float* W1 = (const float*)d_in[13];
    const float* b1 = (const float*)d_in[14];
    const float* W2 = (const float*)d_in[15];
    const float* b2 = (const float*)d_in[16];
    const float* hln_w = (const float*)d_in[17];
    const float* hln_b = (const float*)d_in[18];
    /* Wh1 */ const float* Wh1 = (const float*)d_in[19];
    const float* bh1 = (const float*)d_in[20];
    const float* Wh2 = (const float*)d_in[21];
    const float* bh2 = (const float*)d_in[22];
    float* out = (float*)d_out;

    cudaFuncSetAttribute(fused_kernel, cudaFuncAttributeMaxDynamicSharedMemorySize, SMEM_BYTES);

    prep_kernel<<<512, 256>>>(W_in, W_out, W1, W2, Wh1);
    fused_kernel<<<NB, NT, SMEM_BYTES>>>(k_norm, ctx, W_e, b_e, cls, ln1_w, ln1_b,
                                         b_in, b_out, ln2_w, ln2_b, b1, b2,
                                         hln_w, hln_b, bh1, Wh2, bh2, out);
}